// round 16
// baseline (speedup 1.0000x reference)
#include <cuda_runtime.h>
#include <cuda_bf16.h>
#include <cstdint>
#include <cstddef>

// Problem constants
#define BATCH   2
#define SEQ     2048
#define EMBED   1024
#define HEADS   16
#define HDIM    64
#define MTOT    (BATCH * SEQ)          // 4096
#define ZTOT    (BATCH * HEADS)        // 32
#define OUT_ELEMS   ((size_t)BATCH * SEQ * EMBED)                    // 4,194,304

// ---------------------------------------------------------------------------
// Pre-split bf16 hi/lo scratch
// ---------------------------------------------------------------------------
__device__ __nv_bfloat16 g_Xh[3 * MTOT * EMBED];   // query|key|value
__device__ __nv_bfloat16 g_Xl[3 * MTOT * EMBED];
__device__ __nv_bfloat16 g_Wh[4 * EMBED * EMBED];  // qw|kw|vw|ow
__device__ __nv_bfloat16 g_Wl[4 * EMBED * EMBED];
__device__ __nv_bfloat16 g_Qh[ZTOT * SEQ * HDIM];  // [z][S][64]
__device__ __nv_bfloat16 g_Ql[ZTOT * SEQ * HDIM];
__device__ __nv_bfloat16 g_Kh[ZTOT * SEQ * HDIM];
__device__ __nv_bfloat16 g_Kl[ZTOT * SEQ * HDIM];
__device__ __nv_bfloat16 g_Vth[ZTOT * HDIM * SEQ]; // [z][64][S] (transposed)
__device__ __nv_bfloat16 g_Vtl[ZTOT * HDIM * SEQ];
__device__ __nv_bfloat16 g_AOh[MTOT * EMBED];      // [B,S,E]
__device__ __nv_bfloat16 g_AOl[MTOT * EMBED];
// partial row sums of exp(scores): [z][q][16 k-blocks of 128] (stride 32)
__device__ float g_psum[(size_t)ZTOT * SEQ * 32];

// ===========================================================================
// helpers
// ===========================================================================
__device__ __forceinline__ uint32_t pack_bf16x2(__nv_bfloat16 a, __nv_bfloat16 b) {
    __nv_bfloat162 t;
    t.x = a; t.y = b;
    return *reinterpret_cast<uint32_t*>(&t);
}

__device__ __forceinline__ void split2(float x, float y, uint32_t& h, uint32_t& l) {
    __nv_bfloat16 hx = __float2bfloat16(x);
    __nv_bfloat16 hy = __float2bfloat16(y);
    h = pack_bf16x2(hx, hy);
    l = pack_bf16x2(__float2bfloat16(x - __bfloat162float(hx)),
                    __float2bfloat16(y - __bfloat162float(hy)));
}

// mma.sync m16n8k16 bf16 -> f32, C += A*B
__device__ __forceinline__ void mma16816(float* c, const uint32_t* a, const uint32_t* b) {
    asm volatile(
        "mma.sync.aligned.m16n8k16.row.col.f32.bf16.bf16.f32 "
        "{%0,%1,%2,%3}, {%4,%5,%6,%7}, {%8,%9}, {%0,%1,%2,%3};\n"
        : "+f"(c[0]), "+f"(c[1]), "+f"(c[2]), "+f"(c[3])
        : "r"(a[0]), "r"(a[1]), "r"(a[2]), "r"(a[3]), "r"(b[0]), "r"(b[1]));
}

__device__ __forceinline__ void ldsm4(uint32_t* r, uint32_t saddr) {
    asm volatile("ldmatrix.sync.aligned.m8n8.x4.shared.b16 {%0,%1,%2,%3}, [%4];"
                 : "=r"(r[0]), "=r"(r[1]), "=r"(r[2]), "=r"(r[3]) : "r"(saddr));
}

__device__ __forceinline__ void cp_async16(uint32_t smem_addr, const void* gptr) {
    asm volatile("cp.async.cg.shared.global [%0], [%1], 16;\n"
                 :: "r"(smem_addr), "l"(gptr));
}
#define CP_COMMIT()  asm volatile("cp.async.commit_group;\n" ::: "memory")
#define CP_WAIT0()   asm volatile("cp.async.wait_group 0;\n" ::: "memory")

// smem row stride in u32 for BK=32 tiles: 16 data + 4 pad (conflict-free)
#define SK 20

// ---- big GEMM (128x128) smem layout, u32 units
#define G_STAGE  10240              // (128+128)*SK*2
#define G_AH     0
#define G_AL     2560
#define G_BH     5120
#define G_BL     7680
#define G_EXTRA  20480
#define GEMM_SMEM ((G_EXTRA + 512) * 4)

// ---- av (256x64) smem layout, u32 units
#define AVS_AH   0
#define AVS_AL   5120               // 256*SK
#define AVS_VH   10240
#define AVS_VL   11520              // +64*SK
#define AV_STG   12800
#define AV_SINV  25600
#define AV_SMEM  ((AV_SINV + 256) * 4)

// V-transpose epilogue tile: [128 n][SV u16]
#define SV 136

// ===========================================================================
// prep: split fp32 inputs/weights into bf16 hi/lo once.
// ===========================================================================
__global__ __launch_bounds__(256) void prep_split_kernel(
    const float* __restrict__ q, const float* __restrict__ k,
    const float* __restrict__ v,
    const float* __restrict__ qw, const float* __restrict__ kw,
    const float* __restrict__ vw, const float* __restrict__ ow)
{
    const int z = blockIdx.z;
    const float* src;
    __nv_bfloat16 *dh, *dl;
    int n4;
    if (z < 3) {
        src = (z == 0) ? q : (z == 1) ? k : v;
        dh = g_Xh + (size_t)z * MTOT * EMBED;
        dl = g_Xl + (size_t)z * MTOT * EMBED;
        n4 = MTOT * EMBED / 4;
    } else {
        const int wz = z - 3;
        src = (wz == 0) ? qw : (wz == 1) ? kw : (wz == 2) ? vw : ow;
        dh = g_Wh + (size_t)wz * EMBED * EMBED;
        dl = g_Wl + (size_t)wz * EMBED * EMBED;
        n4 = EMBED * EMBED / 4;
    }
    const int i = blockIdx.x * 256 + threadIdx.x;
    if (i >= n4) return;
    float4 f = ((const float4*)src)[i];
    uint32_t h01, l01, h23, l23;
    split2(f.x, f.y, h01, l01);
    split2(f.z, f.w, h23, l23);
    ((uint2*)dh)[i] = make_uint2(h01, h23);
    ((uint2*)dl)[i] = make_uint2(l01, l23);
}

// ===========================================================================
// Core split-bf16 GEMM tile: C[128,128] = A[128,Kd] * B[128,Kd]^T
// 128 threads, 4 warps as 2m x 2n, warp tile 64x64. cp.async staging.
// mode 0: Cf = acc + bias (fp32)
// mode 1: split-head store to Ch/Cl [z][S][64], + bias
// mode 2: transposed split store to Ch/Cl [z][64][S], + bias (V) via smem
// mode 3: Cf = exp(acc*scale) (unnormalized) + psum partials
// ===========================================================================
__device__ __forceinline__ void gemm_core_s(
    const __nv_bfloat16* __restrict__ Ah_g, const __nv_bfloat16* __restrict__ Al_g,
    const __nv_bfloat16* __restrict__ Bh_g, const __nv_bfloat16* __restrict__ Bl_g,
    const float* __restrict__ bias,
    float* __restrict__ Cf, __nv_bfloat16* __restrict__ Ch,
    __nv_bfloat16* __restrict__ Cl,
    int lda, int ldb, int ldc, int kdim, int mode, float scale,
    int bm, int bn, float* __restrict__ psum, int kb)
{
    extern __shared__ uint32_t dsm[];
    const uint32_t dsma = (uint32_t)__cvta_generic_to_shared(dsm);

    const int tid = threadIdx.x;      // 0..127
    const int w   = tid >> 5;         // 0..3
    const int lid = tid & 31;
    const int g   = lid >> 2;
    const int tg  = lid & 3;
    const int wm  = w >> 1;           // 0..1 (M offset wm*64)
    const int wn  = w & 1;            // 0..1 (N offset wn*64)

    const int a_r = (lid & 7) + ((lid >> 3) & 1) * 8;
    const int a_c = (lid >> 4) * 4;
    const int b_r = (lid & 7) + (lid >> 4) * 8;
    const int b_c = ((lid >> 3) & 1) * 4;

    // staging: 1 thread per A row and per B row (row tid)
    const __nv_bfloat16* aph = Ah_g + (size_t)(bm + tid) * lda;
    const __nv_bfloat16* apl = Al_g + (size_t)(bm + tid) * lda;
    const __nv_bfloat16* bph = Bh_g + (size_t)(bn + tid) * ldb;
    const __nv_bfloat16* bpl = Bl_g + (size_t)(bn + tid) * ldb;

    float c[4][8][4];
#pragma unroll
    for (int mt = 0; mt < 4; ++mt)
#pragma unroll
        for (int nt = 0; nt < 8; ++nt)
#pragma unroll
            for (int i = 0; i < 4; ++i) c[mt][nt][i] = 0.0f;

    auto stage_async = [&](int st, int kt) {
        const uint32_t base = dsma + (st * G_STAGE) * 4;
        const uint32_t rowo = tid * SK * 4;
#pragma unroll
        for (int j = 0; j < 4; ++j) {
            cp_async16(base + (G_AH * 4) + rowo + j * 16, aph + kt + j * 8);
            cp_async16(base + (G_AL * 4) + rowo + j * 16, apl + kt + j * 8);
            cp_async16(base + (G_BH * 4) + rowo + j * 16, bph + kt + j * 8);
            cp_async16(base + (G_BL * 4) + rowo + j * 16, bpl + kt + j * 8);
        }
        CP_COMMIT();
    };

    stage_async(0, 0);
    CP_WAIT0();
    __syncthreads();

    int stg = 0;
#pragma unroll 1
    for (int kt = 0; kt < kdim; kt += 32) {
        const bool nx = (kt + 32 < kdim);
        if (nx) stage_async(stg ^ 1, kt + 32);

        const uint32_t sb = dsma + stg * (G_STAGE * 4);
#pragma unroll
        for (int k16 = 0; k16 < 2; ++k16) {
            const uint32_t ko = k16 * 8 * 4;
            uint32_t bh[4][4], bl[4][4];
#pragma unroll
            for (int np = 0; np < 4; ++np) {
                const uint32_t bo = ((wn * 64 + np * 16 + b_r) * SK + b_c) * 4 + ko;
                ldsm4(bh[np], sb + G_BH * 4 + bo);
                ldsm4(bl[np], sb + G_BL * 4 + bo);
            }
#pragma unroll
            for (int mt = 0; mt < 4; ++mt) {
                uint32_t ah[4], al[4];
                const uint32_t ao = ((wm * 64 + mt * 16 + a_r) * SK + a_c) * 4 + ko;
                ldsm4(ah, sb + ao);
                ldsm4(al, sb + G_AL * 4 + ao);
#pragma unroll
                for (int nt = 0; nt < 8; ++nt)
                    mma16816(c[mt][nt], ah, &bh[nt >> 1][(nt & 1) * 2]);
#pragma unroll
                for (int nt = 0; nt < 8; ++nt)
                    mma16816(c[mt][nt], ah, &bl[nt >> 1][(nt & 1) * 2]);
#pragma unroll
                for (int nt = 0; nt < 8; ++nt)
                    mma16816(c[mt][nt], al, &bh[nt >> 1][(nt & 1) * 2]);
            }
        }

        if (nx) CP_WAIT0();
        __syncthreads();
        stg ^= 1;
    }

    // epilogue
    if (mode == 3) {
        float rs0[4], rs1[4];
#pragma unroll
        for (int mt = 0; mt < 4; ++mt) { rs0[mt] = 0.0f; rs1[mt] = 0.0f; }
#pragma unroll
        for (int mt = 0; mt < 4; ++mt) {
#pragma unroll
            for (int nt = 0; nt < 8; ++nt) {
                const int r0 = bm + wm * 64 + mt * 16 + g;
                const int n0 = bn + wn * 64 + nt * 8 + tg * 2;
                float e0 = __expf(c[mt][nt][0] * scale);
                float e1 = __expf(c[mt][nt][1] * scale);
                float e2 = __expf(c[mt][nt][2] * scale);
                float e3 = __expf(c[mt][nt][3] * scale);
                *(float2*)(Cf + (size_t)r0 * ldc + n0)       = make_float2(e0, e1);
                *(float2*)(Cf + (size_t)(r0 + 8) * ldc + n0) = make_float2(e2, e3);
                rs0[mt] += e0 + e1;
                rs1[mt] += e2 + e3;
            }
        }
#pragma unroll
        for (int o = 1; o <= 2; o <<= 1) {
#pragma unroll
            for (int mt = 0; mt < 4; ++mt) {
                rs0[mt] += __shfl_xor_sync(0xffffffffu, rs0[mt], o);
                rs1[mt] += __shfl_xor_sync(0xffffffffu, rs1[mt], o);
            }
        }
        float* spart = (float*)(dsm + G_EXTRA);   // [128][2]
        if (tg == 0) {
#pragma unroll
            for (int mt = 0; mt < 4; ++mt) {
                spart[(wm * 64 + mt * 16 + g) * 2 + wn]     = rs0[mt];
                spart[(wm * 64 + mt * 16 + g + 8) * 2 + wn] = rs1[mt];
            }
        }
        __syncthreads();
        psum[(size_t)(bm + tid) * 32 + kb] = spart[tid * 2] + spart[tid * 2 + 1];
    } else if (mode == 0) {
#pragma unroll
        for (int mt = 0; mt < 4; ++mt) {
#pragma unroll
            for (int nt = 0; nt < 8; ++nt) {
                const int r0 = bm + wm * 64 + mt * 16 + g;
                const int n0 = bn + wn * 64 + nt * 8 + tg * 2;
                const float2 bb = *(const float2*)&bias[n0];
                *(float2*)(Cf + (size_t)r0 * ldc + n0) =
                    make_float2(c[mt][nt][0] + bb.x, c[mt][nt][1] + bb.y);
                *(float2*)(Cf + (size_t)(r0 + 8) * ldc + n0) =
                    make_float2(c[mt][nt][2] + bb.x, c[mt][nt][3] + bb.y);
            }
        }
    } else if (mode == 1) {
#pragma unroll
        for (int mt = 0; mt < 4; ++mt) {
#pragma unroll
            for (int nt = 0; nt < 8; ++nt) {
                const int r0 = bm + wm * 64 + mt * 16 + g;
                const int n0 = bn + wn * 64 + nt * 8 + tg * 2;
                const float2 bb = *(const float2*)&bias[n0];
                const int hh = n0 >> 6, d = n0 & 63;
                const int b0 = r0 >> 11, s0 = r0 & 2047;
                const int s1 = (r0 + 8) & 2047;
                uint32_t h0, l0, h1, l1;
                split2(c[mt][nt][0] + bb.x, c[mt][nt][1] + bb.y, h0, l0);
                split2(c[mt][nt][2] + bb.x, c[mt][nt][3] + bb.y, h1, l1);
                const size_t o0 = ((size_t)(b0 * HEADS + hh) * SEQ + s0) * HDIM + d;
                const size_t o1 = ((size_t)(b0 * HEADS + hh) * SEQ + s1) * HDIM + d;
                *(uint32_t*)(Ch + o0) = h0;
                *(uint32_t*)(Cl + o0) = l0;
                *(uint32_t*)(Ch + o1) = h1;
                *(uint32_t*)(Cl + o1) = l1;
            }
        }
    } else {
        // mode 2: V transposed split store via smem transpose
        const int b0 = bm >> 11;
        const int s_base = bm & 2047;
        uint16_t* tile = (uint16_t*)dsm;
#pragma unroll 1
        for (int plane = 0; plane < 2; ++plane) {
            __syncthreads();
#pragma unroll
            for (int mt = 0; mt < 4; ++mt) {
#pragma unroll
                for (int nt = 0; nt < 8; ++nt) {
                    const int sl = wm * 64 + mt * 16 + g;
                    const int nl = wn * 64 + nt * 8 + tg * 2;
                    const float2 bb = *(const float2*)&bias[bn + nl];
                    float v00 = c[mt][nt][0] + bb.x, v01 = c[mt][nt][1] + bb.y;
                    float v10 = c[mt][nt][2] + bb.x, v11 = c[mt][nt][3] + bb.y;
                    uint16_t t00, t01, t10, t11;
                    if (plane == 0) {
                        __nv_bfloat16 h;
                        h = __float2bfloat16(v00); t00 = *(uint16_t*)&h;
                        h = __float2bfloat16(v01); t01 = *(uint16_t*)&h;
                        h = __float2bfloat16(v10); t10 = *(uint16_t*)&h;
                        h = __float2bfloat16(v11); t11 = *(uint16_t*)&h;
                    } else {
                        __nv_bfloat16 h, l;
                        h = __float2bfloat16(v00);
                        l = __float2bfloat16(v00 - __bfloat162float(h)); t00 = *(uint16_t*)&l;
                        h = __float2bfloat16(v01);
                        l = __float2bfloat16(v01 - __bfloat162float(h)); t01 = *(uint16_t*)&l;
                        h = __float2bfloat16(v10);
                        l = __float2bfloat16(v10 - __bfloat162float(h)); t10 = *(uint16_t*)&l;
                        h = __float2bfloat16(v11);
                        l = __float2bfloat16(v11 - __bfloat162float(h)); t11 = *(uint16_t*)&l;
                    }
                    tile[(size_t)nl * SV + sl]           = t00;
                    tile[(size_t)(nl + 1) * SV + sl]     = t01;
                    tile[(size_t)nl * SV + sl + 8]       = t10;
                    tile[(size_t)(nl + 1) * SV + sl + 8] = t11;
                }
            }
            __syncthreads();
            // coalesced write-out: thread = one n-row, full 128-s run
            const int gn = bn + tid;
            const int hh = (gn >> 6) & (HEADS - 1);
            const int d  = gn & 63;
            __nv_bfloat16* dst = (plane ? Cl : Ch) +
                ((size_t)(b0 * HEADS + hh) * HDIM + d) * SEQ + s_base;
            const uint16_t* src = tile + (size_t)tid * SV;
#pragma unroll
            for (int j2 = 0; j2 < 16; ++j2)
                *(uint4*)(dst + j2 * 8) = *(const uint4*)(src + j2 * 8);
        }
    }
}

// Generic wrapper (scores mode 3, oproj mode 0)
__global__ __launch_bounds__(128, 2) void gemm_s_kernel(
    const __nv_bfloat16* __restrict__ Ah, const __nv_bfloat16* __restrict__ Al,
    const __nv_bfloat16* __restrict__ Bh, const __nv_bfloat16* __restrict__ Bl,
    const float* __restrict__ bias, float* __restrict__ Cf,
    int lda, int ldb, int ldc, int kdim,
    size_t sAz, size_t sBz, size_t sCz,
    int mode, float scale, float* __restrict__ psum)
{
    const int z = blockIdx.z;
    float* pz = psum ? (psum + (size_t)z * SEQ * 32) : nullptr;
    gemm_core_s(Ah + (size_t)z * sAz, Al + (size_t)z * sAz,
                Bh + (size_t)z * sBz, Bl + (size_t)z * sBz, bias,
                Cf + (size_t)z * sCz, nullptr, nullptr,
                lda, ldb, ldc, kdim, mode, scale,
                blockIdx.y * 128, blockIdx.x * 128, pz, blockIdx.x);
}

// Fused Q/K/V projection
__global__ __launch_bounds__(128, 2) void qkv_proj_kernel(
    const float* __restrict__ qb, const float* __restrict__ kb,
    const float* __restrict__ vb)
{
    const int z = blockIdx.z;
    const __nv_bfloat16* Ah = g_Xh + (size_t)z * MTOT * EMBED;
    const __nv_bfloat16* Al = g_Xl + (size_t)z * MTOT * EMBED;
    const __nv_bfloat16* Bh = g_Wh + (size_t)z * EMBED * EMBED;
    const __nv_bfloat16* Bl = g_Wl + (size_t)z * EMBED * EMBED;
    const float* bias = (z == 0) ? qb : (z == 1) ? kb : vb;
    __nv_bfloat16 *Ch, *Cl;
    int mode;
    if (z == 0)      { Ch = g_Qh;  Cl = g_Ql;  mode = 1; }
    else if (z == 1) { Ch = g_Kh;  Cl = g_Kl;  mode = 1; }
    else             { Ch = g_Vth; Cl = g_Vtl; mode = 2; }
    gemm_core_s(Ah, Al, Bh, Bl, bias, nullptr, Ch, Cl,
                EMBED, EMBED, 0, EMBED, mode, 1.0f,
                blockIdx.y * 128, blockIdx.x * 128, nullptr, 0);
}

// ===========================================================================
// av: tile 256(q) x 64(d), 256 threads, 8 warps as 4m x 2n (warp 64x32).
// Normalizes attn in place, AO = P_norm @ V, split-bf16 AO output.
// V staged via cp.async; A staged 1 thread/row with LDG->normalize->STS.
// ===========================================================================
__global__ __launch_bounds__(256, 1) void av_mma_kernel(
    float* __restrict__ attn, const float* __restrict__ psum)
{
    extern __shared__ uint32_t dsm[];
    const uint32_t dsma = (uint32_t)__cvta_generic_to_shared(dsm);
    float* s_inv = (float*)(dsm + AV_SINV);   // [256]

    const int tid = threadIdx.x;
    const int w   = tid >> 5;
    const int lid = tid & 31;
    const int g   = lid >> 2;
    const int tg  = lid & 3;
    const int wm  = w >> 1;        // 0..3 (M offset wm*64)
    const int wn  = w & 1;         // 0..1 (N offset wn*32)

    const int a_r = (lid & 7) + ((lid >> 3) & 1) * 8;
    const int a_c = (lid >> 4) * 4;
    const int b_r = (lid & 7) + (lid >> 4) * 8;
    const int b_c = ((lid >> 3) & 1) * 4;

    const int z  = blockIdx.y;
    const int bm = blockIdx.x * 256;

    float* Wp = attn + (size_t)z * SEQ * SEQ + (size_t)bm * SEQ;
    const __nv_bfloat16* Vph = g_Vth + (size_t)z * HDIM * SEQ;
    const __nv_bfloat16* Vpl = g_Vtl + (size_t)z * HDIM * SEQ;

    // row inverse sums (deterministic)
    {
        const float* pp = psum + ((size_t)z * SEQ + bm + tid) * 32;
        float s = 0.0f;
#pragma unroll
        for (int i = 0; i < 16; ++i) s += pp[i];
        s_inv[tid] = 1.0f / s;
    }
    __syncthreads();

    // A: 1 thread per row (row tid)
    float* apw = Wp + (size_t)tid * SEQ;
    const float inv = s_inv[tid];

    // V cp.async mapping: 4 threads/row, 16B chunks
    const int vrow = tid >> 2;            // 0..63
    const int vch  = tid & 3;             // chunk
    const __nv_bfloat16* vph = Vph + (size_t)vrow * SEQ + vch * 8;
    const __nv_bfloat16* vpl = Vpl + (size_t)vrow * SEQ + vch * 8;
    const uint32_t vdst = (vrow * SK + vch * 4) * 4;

    float c[4][4][4];
#pragma unroll
    for (int mt = 0; mt < 4; ++mt)
#pragma unroll
        for (int nt = 0; nt < 4; ++nt)
#pragma unroll
            for (int i = 0; i < 4; ++i) c[mt][nt][i] = 0.0f;

    float4 pa[8];

    auto v_async = [&](int st, int kt) {
        const uint32_t base = dsma + (st * AV_STG) * 4;
        cp_async16(base + AVS_VH * 4 + vdst, vph + kt);
        cp_async16(base + AVS_VL * 4 + vdst, vpl + kt);
        CP_COMMIT();
    };
    auto a_ldg = [&](int kt) {
#pragma unroll
        for (int j = 0; j < 8; ++j)
            pa[j] = *(const float4*)(apw + kt + j * 4);
    };
    // normalize + writeback + STS (consumes pa)
    auto a_stage = [&](int st, int kt) {
        uint32_t* base = dsm + st * AV_STG;
#pragma unroll
        for (int jj = 0; jj < 4; ++jj) {
            float4 v0 = make_float4(pa[2 * jj].x * inv, pa[2 * jj].y * inv,
                                    pa[2 * jj].z * inv, pa[2 * jj].w * inv);
            float4 v1 = make_float4(pa[2 * jj + 1].x * inv, pa[2 * jj + 1].y * inv,
                                    pa[2 * jj + 1].z * inv, pa[2 * jj + 1].w * inv);
            *(float4*)(apw + kt + jj * 8)     = v0;
            *(float4*)(apw + kt + jj * 8 + 4) = v1;
            uint4 hq, lq;
            split2(v0.x, v0.y, hq.x, lq.x);
            split2(v0.z, v0.w, hq.y, lq.y);
            split2(v1.x, v1.y, hq.z, lq.z);
            split2(v1.z, v1.w, hq.w, lq.w);
            *(uint4*)&base[AVS_AH + tid * SK + jj * 4] = hq;
            *(uint4*)&base[AVS_AL + tid * SK + jj * 4] = lq;
        }
    };

    // prologue: slab 0
    v_async(0, 0);
    a_ldg(0);
    a_stage(0, 0);
    CP_WAIT0();
    __syncthreads();

    int stg = 0;
#pragma unroll 1
    for (int kt = 0; kt < SEQ; kt += 32) {
        const bool nx = (kt + 32 < SEQ);
        if (nx) {
            v_async(stg ^ 1, kt + 32);
            a_ldg(kt + 32);
        }

        const uint32_t sb = dsma + stg * (AV_STG * 4);
#pragma unroll
        for (int k16 = 0; k16 < 2; ++k16) {
            const uint32_t ko = k16 * 8 * 4;
            uint32_t bh[2][4], bl[2][4];
#pragma unroll
            for (int np = 0; np < 2; ++np) {
                const uint32_t bo = ((wn * 32 + np * 16 + b_r) * SK + b_c) * 4 + ko;
                ldsm4(bh[np], sb + AVS_VH * 4 + bo);
                ldsm4(bl[np], sb + AVS_VL * 4 + bo);
            }
#pragma unroll
            for (int mt = 0; mt < 4; ++mt) {
                uint32_t ah[4], al[4];
                const uint32_t ao = ((wm * 64 + mt * 16 + a_r) * SK + a_c) * 4 + ko;
                ldsm4(ah, sb + AVS_AH * 4 + ao);
                ldsm4(al, sb + AVS_AL * 4 + ao);
#pragma unroll
                for (int nt = 0; nt < 4; ++nt)
                    mma16816(c[mt][nt], ah, &bh[nt >> 1][(nt & 1) * 2]);
#pragma unroll
                for (int nt = 0; nt < 4; ++nt)
                    mma16816(c[mt][nt], ah, &bl[nt >> 1][(nt & 1) * 2]);
#pragma unroll
                for (int nt = 0; nt < 4; ++nt)
                    mma16816(c[mt][nt], al, &bh[nt >> 1][(nt & 1) * 2]);
            }
        }

        if (nx) {
            a_stage(stg ^ 1, kt + 32);
            CP_WAIT0();
        }
        __syncthreads();
        stg ^= 1;
    }

    const int b = z >> 4, hh = z & 15;
#pragma unroll
    for (int mt = 0; mt < 4; ++mt) {
#pragma unroll
        for (int nt = 0; nt < 4; ++nt) {
            const int q0 = bm + wm * 64 + mt * 16 + g;
            const int d0 = wn * 32 + nt * 8 + tg * 2;
            const size_t o0 = ((size_t)(b * SEQ + q0)) * EMBED + hh * HDIM + d0;
            const size_t o1 = ((size_t)(b * SEQ + q0 + 8)) * EMBED + hh * HDIM + d0;
            uint32_t h0, l0, h1, l1;
            split2(c[mt][nt][0], c[mt][nt][1], h0, l0);
            split2(c[mt][nt][2], c[mt][nt][3], h1, l1);
            *(uint32_t*)(g_AOh + o0) = h0;
            *(uint32_t*)(g_AOl + o0) = l0;
            *(uint32_t*)(g_AOh + o1) = h1;
            *(uint32_t*)(g_AOl + o1) = l1;
        }
    }
}

// ---------------------------------------------------------------------------
// launch
// ---------------------------------------------------------------------------
extern "C" void kernel_launch(void* const* d_in, const int* in_sizes, int n_in,
                              void* d_out, int out_size)
{
    (void)in_sizes; (void)n_in; (void)out_size;
    const float* query = (const float*)d_in[0];
    const float* key   = (const float*)d_in[1];
    const float* value = (const float*)d_in[2];
    const float* q_w   = (const float*)d_in[3];
    const float* q_b   = (const float*)d_in[4];
    const float* k_w   = (const float*)d_in[5];
    const float* k_b   = (const float*)d_in[6];
    const float* v_w   = (const float*)d_in[7];
    const float* v_b   = (const float*)d_in[8];
    const float* o_w   = (const float*)d_in[9];
    const float* o_b   = (const float*)d_in[10];

    float* out  = (float*)d_out;                 // [B,S,E]
    float* attn = out + OUT_ELEMS;               // [B,H,S,S]

    float* pPS;
    cudaGetSymbolAddress((void**)&pPS, g_psum);
    __nv_bfloat16 *pAOh, *pAOl, *pQh, *pQl, *pKh, *pKl, *pWh, *pWl;
    cudaGetSymbolAddress((void**)&pAOh, g_AOh);
    cudaGetSymbolAddress((void**)&pAOl, g_AOl);
    cudaGetSymbolAddress((void**)&pQh, g_Qh);
    cudaGetSymbolAddress((void**)&pQl, g_Ql);
    cudaGetSymbolAddress((void**)&pKh, g_Kh);
    cudaGetSymbolAddress((void**)&pKl, g_Kl);
    cudaGetSymbolAddress((void**)&pWh, g_Wh);
    cudaGetSymbolAddress((void**)&pWl, g_Wl);

    static bool attr_done = false;
    if (!attr_done) {
        cudaFuncSetAttribute(qkv_proj_kernel,
                             cudaFuncAttributeMaxDynamicSharedMemorySize, GEMM_SMEM);
        cudaFuncSetAttribute(gemm_s_kernel,
                             cudaFuncAttributeMaxDynamicSharedMemorySize, GEMM_SMEM);
        cudaFuncSetAttribute(av_mma_kernel,
                             cudaFuncAttributeMaxDynamicSharedMemorySize, AV_SMEM);
        attr_done = true;
    }

    // 0) split all fp32 operands into bf16 hi/lo once
    dim3 pgrid(MTOT * EMBED / 4 / 256, 1, 7);
    prep_split_kernel<<<pgrid, 256>>>(query, key, value, q_w, k_w, v_w, o_w);

    // 1) fused Q/K/V projections (split-bf16 outputs; V transposed)
    dim3 qkvgrid(EMBED / 128, MTOT / 128, 3);    // (8, 32, 3)
    qkv_proj_kernel<<<qkvgrid, 128, GEMM_SMEM>>>(q_b, k_b, v_b);

    // 2) scores: attn[z] = exp((Q_z @ K_z^T) * 0.125) unnormalized + psum
    dim3 sgrid(SEQ / 128, SEQ / 128, ZTOT);      // (16, 16, 32)
    gemm_s_kernel<<<sgrid, 128, GEMM_SMEM>>>(pQh, pQl, pKh, pKl, nullptr, attn,
                                             HDIM, HDIM, SEQ, HDIM,
                                             (size_t)SEQ * HDIM, (size_t)SEQ * HDIM,
                                             (size_t)SEQ * SEQ, 3, 0.125f, pPS);

    // 3) av: normalize attn in place + AO = P @ V (split outputs)
    dim3 avgrid(SEQ / 256, ZTOT);                // (8, 32)
    av_mma_kernel<<<avgrid, 256, AV_SMEM>>>(attn, pPS);

    // 4) output projection (fp32 out + bias)
    dim3 ogrid(EMBED / 128, MTOT / 128, 1);      // (8, 32)
    gemm_s_kernel<<<ogrid, 128, GEMM_SMEM>>>(pAOh, pAOl,
                                             pWh + (size_t)3 * EMBED * EMBED,
                                             pWl + (size_t)3 * EMBED * EMBED,
                                             o_b, out,
                                             EMBED, EMBED, EMBED, EMBED, 0, 0, 0,
                                             0, 1.0f, nullptr);
}

// round 17
// speedup vs baseline: 1.1542x; 1.1542x over previous
#include <cuda_runtime.h>
#include <cuda_bf16.h>
#include <cstdint>
#include <cstddef>

// Problem constants
#define BATCH   2
#define SEQ     2048
#define EMBED   1024
#define HEADS   16
#define HDIM    64
#define MTOT    (BATCH * SEQ)          // 4096
#define ZTOT    (BATCH * HEADS)        // 32
#define OUT_ELEMS   ((size_t)BATCH * SEQ * EMBED)                    // 4,194,304

// ---------------------------------------------------------------------------
// Pre-split bf16 hi/lo scratch (split once, consumed by all GEMMs)
// ---------------------------------------------------------------------------
__device__ __nv_bfloat16 g_Xh[3 * MTOT * EMBED];   // query|key|value
__device__ __nv_bfloat16 g_Xl[3 * MTOT * EMBED];
__device__ __nv_bfloat16 g_Wh[4 * EMBED * EMBED];  // qw|kw|vw|ow
__device__ __nv_bfloat16 g_Wl[4 * EMBED * EMBED];
__device__ __nv_bfloat16 g_Qh[ZTOT * SEQ * HDIM];  // [z][S][64]
__device__ __nv_bfloat16 g_Ql[ZTOT * SEQ * HDIM];
__device__ __nv_bfloat16 g_Kh[ZTOT * SEQ * HDIM];
__device__ __nv_bfloat16 g_Kl[ZTOT * SEQ * HDIM];
__device__ __nv_bfloat16 g_Vth[ZTOT * HDIM * SEQ]; // [z][64][S] (transposed)
__device__ __nv_bfloat16 g_Vtl[ZTOT * HDIM * SEQ];
__device__ __nv_bfloat16 g_AOh[MTOT * EMBED];      // [B,S,E]
__device__ __nv_bfloat16 g_AOl[MTOT * EMBED];
// partial row sums of exp(scores): [z][q][16 k-blocks of 128] (stride 32)
__device__ float g_psum[(size_t)ZTOT * SEQ * 32];

// ===========================================================================
// helpers
// ===========================================================================
__device__ __forceinline__ uint32_t pack_bf16x2(__nv_bfloat16 a, __nv_bfloat16 b) {
    __nv_bfloat162 t;
    t.x = a; t.y = b;
    return *reinterpret_cast<uint32_t*>(&t);
}

__device__ __forceinline__ void split2(float x, float y, uint32_t& h, uint32_t& l) {
    __nv_bfloat16 hx = __float2bfloat16(x);
    __nv_bfloat16 hy = __float2bfloat16(y);
    h = pack_bf16x2(hx, hy);
    l = pack_bf16x2(__float2bfloat16(x - __bfloat162float(hx)),
                    __float2bfloat16(y - __bfloat162float(hy)));
}

// mma.sync m16n8k16 bf16 -> f32, C += A*B
__device__ __forceinline__ void mma16816(float* c, const uint32_t* a, const uint32_t* b) {
    asm volatile(
        "mma.sync.aligned.m16n8k16.row.col.f32.bf16.bf16.f32 "
        "{%0,%1,%2,%3}, {%4,%5,%6,%7}, {%8,%9}, {%0,%1,%2,%3};\n"
        : "+f"(c[0]), "+f"(c[1]), "+f"(c[2]), "+f"(c[3])
        : "r"(a[0]), "r"(a[1]), "r"(a[2]), "r"(a[3]), "r"(b[0]), "r"(b[1]));
}

__device__ __forceinline__ void ldsm4(uint32_t* r, uint32_t saddr) {
    asm volatile("ldmatrix.sync.aligned.m8n8.x4.shared.b16 {%0,%1,%2,%3}, [%4];"
                 : "=r"(r[0]), "=r"(r[1]), "=r"(r[2]), "=r"(r[3]) : "r"(saddr));
}

__device__ __forceinline__ void cp_async16(uint32_t smem_addr, const void* gptr) {
    asm volatile("cp.async.cg.shared.global [%0], [%1], 16;\n"
                 :: "r"(smem_addr), "l"(gptr));
}
#define CP_COMMIT()  asm volatile("cp.async.commit_group;\n" ::: "memory")
#define CP_WAIT0()   asm volatile("cp.async.wait_group 0;\n" ::: "memory")

// smem row stride in u32 for BK=32 tiles: 16 data + 4 pad (conflict-free)
#define SK 20

// ---- big GEMM (128x128) smem layout, u32 units
#define G_STAGE  10240              // (128+128)*SK*2
#define G_AH     0
#define G_AL     2560
#define G_BH     5120
#define G_BL     7680
#define G_EXTRA  20480
#define GEMM_SMEM ((G_EXTRA + 512) * 4)

// ---- av (128x64) smem layout
#define AV_STAGE 7680               // 128*SK*2 + 64*SK*2
#define AV_EXTRA 15360
#define AV_SMEM  ((AV_EXTRA + 128) * 4)

// ===========================================================================
// prep: split fp32 inputs/weights into bf16 hi/lo once.
// ===========================================================================
__global__ __launch_bounds__(256) void prep_split_kernel(
    const float* __restrict__ q, const float* __restrict__ k,
    const float* __restrict__ v,
    const float* __restrict__ qw, const float* __restrict__ kw,
    const float* __restrict__ vw, const float* __restrict__ ow)
{
    const int z = blockIdx.z;
    const float* src;
    __nv_bfloat16 *dh, *dl;
    int n4;
    if (z < 3) {
        src = (z == 0) ? q : (z == 1) ? k : v;
        dh = g_Xh + (size_t)z * MTOT * EMBED;
        dl = g_Xl + (size_t)z * MTOT * EMBED;
        n4 = MTOT * EMBED / 4;
    } else {
        const int wz = z - 3;
        src = (wz == 0) ? qw : (wz == 1) ? kw : (wz == 2) ? vw : ow;
        dh = g_Wh + (size_t)wz * EMBED * EMBED;
        dl = g_Wl + (size_t)wz * EMBED * EMBED;
        n4 = EMBED * EMBED / 4;
    }
    const int i = blockIdx.x * 256 + threadIdx.x;
    if (i >= n4) return;
    float4 f = ((const float4*)src)[i];
    uint32_t h01, l01, h23, l23;
    split2(f.x, f.y, h01, l01);
    split2(f.z, f.w, h23, l23);
    ((uint2*)dh)[i] = make_uint2(h01, h23);
    ((uint2*)dl)[i] = make_uint2(l01, l23);
}

// ===========================================================================
// Core split-bf16 GEMM tile: C[128, 128] = A[128, Kd] * B[128, Kd]^T
// 256 threads, 8 warps as 2m x 4n, warp tile 64x32.  (R14 configuration)
// mode 0: Cf = acc + bias (fp32)
// mode 1: split-head store to Ch/Cl [z][S][64], + bias
// mode 2: transposed split store to Ch/Cl [z][64][S], + bias (V)
// mode 3: Cf = exp(acc*scale) (unnormalized) + psum partials
// ===========================================================================
__device__ __forceinline__ void gemm_core_s(
    const __nv_bfloat16* __restrict__ Ah_g, const __nv_bfloat16* __restrict__ Al_g,
    const __nv_bfloat16* __restrict__ Bh_g, const __nv_bfloat16* __restrict__ Bl_g,
    const float* __restrict__ bias,
    float* __restrict__ Cf, __nv_bfloat16* __restrict__ Ch,
    __nv_bfloat16* __restrict__ Cl,
    int lda, int ldb, int ldc, int kdim, int mode, float scale,
    int bm, int bn, float* __restrict__ psum, int kb)
{
    extern __shared__ uint32_t dsm[];
    const uint32_t dsma = (uint32_t)__cvta_generic_to_shared(dsm);

    const int tid = threadIdx.x;
    const int w   = tid >> 5;
    const int lid = tid & 31;
    const int g   = lid >> 2;
    const int tg  = lid & 3;
    const int wm  = w >> 2;        // 0..1
    const int wn  = w & 3;         // 0..3

    const int a_r = (lid & 7) + ((lid >> 3) & 1) * 8;
    const int a_c = (lid >> 4) * 4;
    const int b_r = (lid & 7) + (lid >> 4) * 8;
    const int b_c = ((lid >> 3) & 1) * 4;

    const int srow = tid >> 1;
    const int ssu  = (tid & 1) * 8;
    const __nv_bfloat16* aph = Ah_g + (size_t)(bm + srow) * lda + ssu * 2;
    const __nv_bfloat16* apl = Al_g + (size_t)(bm + srow) * lda + ssu * 2;
    const __nv_bfloat16* bph = Bh_g + (size_t)(bn + srow) * ldb + ssu * 2;
    const __nv_bfloat16* bpl = Bl_g + (size_t)(bn + srow) * ldb + ssu * 2;

    float c[4][4][4];
#pragma unroll
    for (int mt = 0; mt < 4; ++mt)
#pragma unroll
        for (int nt = 0; nt < 4; ++nt)
#pragma unroll
            for (int i = 0; i < 4; ++i) c[mt][nt][i] = 0.0f;

    uint4 pah[2], pal[2], pbh[2], pbl[2];
    pah[0] = *(const uint4*)(aph);     pah[1] = *(const uint4*)(aph + 8);
    pal[0] = *(const uint4*)(apl);     pal[1] = *(const uint4*)(apl + 8);
    pbh[0] = *(const uint4*)(bph);     pbh[1] = *(const uint4*)(bph + 8);
    pbl[0] = *(const uint4*)(bpl);     pbl[1] = *(const uint4*)(bpl + 8);

    auto stage = [&](int st) {
        uint32_t* b0 = dsm + st * G_STAGE;
        *(uint4*)&b0[G_AH + srow * SK + ssu]     = pah[0];
        *(uint4*)&b0[G_AH + srow * SK + ssu + 4] = pah[1];
        *(uint4*)&b0[G_AL + srow * SK + ssu]     = pal[0];
        *(uint4*)&b0[G_AL + srow * SK + ssu + 4] = pal[1];
        *(uint4*)&b0[G_BH + srow * SK + ssu]     = pbh[0];
        *(uint4*)&b0[G_BH + srow * SK + ssu + 4] = pbh[1];
        *(uint4*)&b0[G_BL + srow * SK + ssu]     = pbl[0];
        *(uint4*)&b0[G_BL + srow * SK + ssu + 4] = pbl[1];
    };
    stage(0);
    __syncthreads();

    int stg = 0;
#pragma unroll 1
    for (int kt = 0; kt < kdim; kt += 32) {
        const bool nx = (kt + 32 < kdim);
        if (nx) {
            pah[0] = *(const uint4*)(aph + kt + 32); pah[1] = *(const uint4*)(aph + kt + 40);
            pal[0] = *(const uint4*)(apl + kt + 32); pal[1] = *(const uint4*)(apl + kt + 40);
            pbh[0] = *(const uint4*)(bph + kt + 32); pbh[1] = *(const uint4*)(bph + kt + 40);
            pbl[0] = *(const uint4*)(bpl + kt + 32); pbl[1] = *(const uint4*)(bpl + kt + 40);
        }

        const uint32_t sb = dsma + stg * (G_STAGE * 4);
        const uint32_t aAh = sb + ((a_r) * SK + a_c) * 4 + (wm * 64) * (SK * 4);
        const uint32_t aAl = aAh + G_AL * 4;
        const uint32_t aBh = sb + G_BH * 4 + ((wn * 32 + b_r) * SK + b_c) * 4;
        const uint32_t aBl = aBh + (G_BL - G_BH) * 4;

#pragma unroll
        for (int k16 = 0; k16 < 2; ++k16) {
            const uint32_t ko = k16 * 8 * 4;
            uint32_t ah[4][4], al[4][4], bh[2][4], bl[2][4];
#pragma unroll
            for (int mt = 0; mt < 4; ++mt) {
                ldsm4(ah[mt], aAh + mt * (16 * SK * 4) + ko);
                ldsm4(al[mt], aAl + mt * (16 * SK * 4) + ko);
            }
#pragma unroll
            for (int np = 0; np < 2; ++np) {
                ldsm4(bh[np], aBh + np * (16 * SK * 4) + ko);
                ldsm4(bl[np], aBl + np * (16 * SK * 4) + ko);
            }
#pragma unroll
            for (int mt = 0; mt < 4; ++mt)
#pragma unroll
                for (int nt = 0; nt < 4; ++nt)
                    mma16816(c[mt][nt], ah[mt], &bh[nt >> 1][(nt & 1) * 2]);
#pragma unroll
            for (int mt = 0; mt < 4; ++mt)
#pragma unroll
                for (int nt = 0; nt < 4; ++nt)
                    mma16816(c[mt][nt], ah[mt], &bl[nt >> 1][(nt & 1) * 2]);
#pragma unroll
            for (int mt = 0; mt < 4; ++mt)
#pragma unroll
                for (int nt = 0; nt < 4; ++nt)
                    mma16816(c[mt][nt], al[mt], &bh[nt >> 1][(nt & 1) * 2]);
        }

        if (nx) stage(stg ^ 1);
        __syncthreads();
        stg ^= 1;
    }

    // epilogue
    if (mode == 3) {
        float rs0[4], rs1[4];
#pragma unroll
        for (int mt = 0; mt < 4; ++mt) { rs0[mt] = 0.0f; rs1[mt] = 0.0f; }
#pragma unroll
        for (int mt = 0; mt < 4; ++mt) {
#pragma unroll
            for (int nt = 0; nt < 4; ++nt) {
                const int r0 = bm + wm * 64 + mt * 16 + g;
                const int n0 = bn + wn * 32 + nt * 8 + tg * 2;
                float e0 = __expf(c[mt][nt][0] * scale);
                float e1 = __expf(c[mt][nt][1] * scale);
                float e2 = __expf(c[mt][nt][2] * scale);
                float e3 = __expf(c[mt][nt][3] * scale);
                *(float2*)(Cf + (size_t)r0 * ldc + n0)       = make_float2(e0, e1);
                *(float2*)(Cf + (size_t)(r0 + 8) * ldc + n0) = make_float2(e2, e3);
                rs0[mt] += e0 + e1;
                rs1[mt] += e2 + e3;
            }
        }
#pragma unroll
        for (int o = 1; o <= 2; o <<= 1) {
#pragma unroll
            for (int mt = 0; mt < 4; ++mt) {
                rs0[mt] += __shfl_xor_sync(0xffffffffu, rs0[mt], o);
                rs1[mt] += __shfl_xor_sync(0xffffffffu, rs1[mt], o);
            }
        }
        float* spart = (float*)(dsm + G_EXTRA);   // [128][4]
        if (tg == 0) {
#pragma unroll
            for (int mt = 0; mt < 4; ++mt) {
                spart[(wm * 64 + mt * 16 + g) * 4 + wn]     = rs0[mt];
                spart[(wm * 64 + mt * 16 + g + 8) * 4 + wn] = rs1[mt];
            }
        }
        __syncthreads();
        if (tid < 128) {
            const float* sp = spart + tid * 4;
            psum[(size_t)(bm + tid) * 32 + kb] = (sp[0] + sp[1]) + (sp[2] + sp[3]);
        }
    } else if (mode == 0) {
#pragma unroll
        for (int mt = 0; mt < 4; ++mt) {
#pragma unroll
            for (int nt = 0; nt < 4; ++nt) {
                const int r0 = bm + wm * 64 + mt * 16 + g;
                const int n0 = bn + wn * 32 + nt * 8 + tg * 2;
                const float2 bb = *(const float2*)&bias[n0];
                *(float2*)(Cf + (size_t)r0 * ldc + n0) =
                    make_float2(c[mt][nt][0] + bb.x, c[mt][nt][1] + bb.y);
                *(float2*)(Cf + (size_t)(r0 + 8) * ldc + n0) =
                    make_float2(c[mt][nt][2] + bb.x, c[mt][nt][3] + bb.y);
            }
        }
    } else if (mode == 1) {
#pragma unroll
        for (int mt = 0; mt < 4; ++mt) {
#pragma unroll
            for (int nt = 0; nt < 4; ++nt) {
                const int r0 = bm + wm * 64 + mt * 16 + g;
                const int n0 = bn + wn * 32 + nt * 8 + tg * 2;
                const float2 bb = *(const float2*)&bias[n0];
                const int hh = n0 >> 6, d = n0 & 63;
                const int b0 = r0 >> 11, s0 = r0 & 2047;
                const int s1 = (r0 + 8) & 2047;
                uint32_t h0, l0, h1, l1;
                split2(c[mt][nt][0] + bb.x, c[mt][nt][1] + bb.y, h0, l0);
                split2(c[mt][nt][2] + bb.x, c[mt][nt][3] + bb.y, h1, l1);
                const size_t o0 = ((size_t)(b0 * HEADS + hh) * SEQ + s0) * HDIM + d;
                const size_t o1 = ((size_t)(b0 * HEADS + hh) * SEQ + s1) * HDIM + d;
                *(uint32_t*)(Ch + o0) = h0;
                *(uint32_t*)(Cl + o0) = l0;
                *(uint32_t*)(Ch + o1) = h1;
                *(uint32_t*)(Cl + o1) = l1;
            }
        }
    } else {  // mode 2: V transposed split store [z][64][S]
#pragma unroll
        for (int mt = 0; mt < 4; ++mt) {
#pragma unroll
            for (int nt = 0; nt < 4; ++nt) {
                const int r0 = bm + wm * 64 + mt * 16 + g;
                const int n0 = bn + wn * 32 + nt * 8 + tg * 2;
                const float2 bb = *(const float2*)&bias[n0];
                const int hh = n0 >> 6, d = n0 & 63;
                const int b0 = r0 >> 11, s0 = r0 & 2047;
                const int s1 = (r0 + 8) & 2047;
                const size_t zb = (size_t)(b0 * HEADS + hh) * HDIM;
                float v00 = c[mt][nt][0] + bb.x, v01 = c[mt][nt][1] + bb.y;
                float v10 = c[mt][nt][2] + bb.x, v11 = c[mt][nt][3] + bb.y;
                __nv_bfloat16 h;
                h = __float2bfloat16(v00);
                Ch[(zb + d) * SEQ + s0] = h;
                Cl[(zb + d) * SEQ + s0] = __float2bfloat16(v00 - __bfloat162float(h));
                h = __float2bfloat16(v01);
                Ch[(zb + d + 1) * SEQ + s0] = h;
                Cl[(zb + d + 1) * SEQ + s0] = __float2bfloat16(v01 - __bfloat162float(h));
                h = __float2bfloat16(v10);
                Ch[(zb + d) * SEQ + s1] = h;
                Cl[(zb + d) * SEQ + s1] = __float2bfloat16(v10 - __bfloat162float(h));
                h = __float2bfloat16(v11);
                Ch[(zb + d + 1) * SEQ + s1] = h;
                Cl[(zb + d + 1) * SEQ + s1] = __float2bfloat16(v11 - __bfloat162float(h));
            }
        }
    }
}

// Generic wrapper with z-strides (scores mode 3, oproj mode 0)
__global__ __launch_bounds__(256, 1) void gemm_s_kernel(
    const __nv_bfloat16* __restrict__ Ah, const __nv_bfloat16* __restrict__ Al,
    const __nv_bfloat16* __restrict__ Bh, const __nv_bfloat16* __restrict__ Bl,
    const float* __restrict__ bias, float* __restrict__ Cf,
    int lda, int ldb, int ldc, int kdim,
    size_t sAz, size_t sBz, size_t sCz,
    int mode, float scale, float* __restrict__ psum)
{
    const int z = blockIdx.z;
    float* pz = psum ? (psum + (size_t)z * SEQ * 32) : nullptr;
    gemm_core_s(Ah + (size_t)z * sAz, Al + (size_t)z * sAz,
                Bh + (size_t)z * sBz, Bl + (size_t)z * sBz, bias,
                Cf + (size_t)z * sCz, nullptr, nullptr,
                lda, ldb, ldc, kdim, mode, scale,
                blockIdx.y * 128, blockIdx.x * 128, pz, blockIdx.x);
}

// Fused Q/K/V projection: z selects projection; outputs split bf16.
__global__ __launch_bounds__(256, 1) void qkv_proj_kernel(
    const float* __restrict__ qb, const float* __restrict__ kb,
    const float* __restrict__ vb)
{
    const int z = blockIdx.z;
    const __nv_bfloat16* Ah = g_Xh + (size_t)z * MTOT * EMBED;
    const __nv_bfloat16* Al = g_Xl + (size_t)z * MTOT * EMBED;
    const __nv_bfloat16* Bh = g_Wh + (size_t)z * EMBED * EMBED;
    const __nv_bfloat16* Bl = g_Wl + (size_t)z * EMBED * EMBED;
    const float* bias = (z == 0) ? qb : (z == 1) ? kb : vb;
    __nv_bfloat16 *Ch, *Cl;
    int mode;
    if (z == 0)      { Ch = g_Qh;  Cl = g_Ql;  mode = 1; }
    else if (z == 1) { Ch = g_Kh;  Cl = g_Kl;  mode = 1; }
    else             { Ch = g_Vth; Cl = g_Vtl; mode = 2; }
    gemm_core_s(Ah, Al, Bh, Bl, bias, nullptr, Ch, Cl,
                EMBED, EMBED, 0, EMBED, mode, 1.0f,
                blockIdx.y * 128, blockIdx.x * 128, nullptr, 0);
}

// ===========================================================================
// av (R14 config + cp.async V path): tile 128(q) x 64(d), 256 threads,
// 8 warps as 4m x 2n (warp 32x32), occ 2, double-buffered.
// Normalizes attn in place; AO = P_norm @ V; split-bf16 AO output.
// ===========================================================================
__global__ __launch_bounds__(256, 2) void av_mma_kernel(
    float* __restrict__ attn, const float* __restrict__ psum)
{
    extern __shared__ uint32_t dsm[];
    const uint32_t dsma = (uint32_t)__cvta_generic_to_shared(dsm);
    float* s_inv = (float*)(dsm + AV_EXTRA);   // [128]

    const int tid = threadIdx.x;
    const int w   = tid >> 5;
    const int lid = tid & 31;
    const int g   = lid >> 2;
    const int tg  = lid & 3;
    const int wm  = w >> 1;        // 0..3
    const int wn  = w & 1;         // 0..1

    const int a_r = (lid & 7) + ((lid >> 3) & 1) * 8;
    const int a_c = (lid >> 4) * 4;
    const int b_r = (lid & 7) + (lid >> 4) * 8;
    const int b_c = ((lid >> 3) & 1) * 4;

    const int z  = blockIdx.y;
    const int bm = blockIdx.x * 128;

    float* Wp = attn + (size_t)z * SEQ * SEQ + (size_t)bm * SEQ;
    const __nv_bfloat16* Vph = g_Vth + (size_t)z * HDIM * SEQ;
    const __nv_bfloat16* Vpl = g_Vtl + (size_t)z * HDIM * SEQ;

    if (tid < 128) {
        const float* pp = psum + ((size_t)z * SEQ + bm + tid) * 32;
        float s = 0.0f;
#pragma unroll
        for (int i = 0; i < 16; ++i) s += pp[i];
        s_inv[tid] = 1.0f / s;
    }
    __syncthreads();

    const int arow = tid >> 1;
    const int asu  = (tid & 1) * 8;
    float* apw = Wp + (size_t)arow * SEQ + asu * 2;
    const float inv = s_inv[arow];

    // V via cp.async: 4 threads/row(d), one 16B chunk per plane per thread
    const int vrow = tid >> 2;            // d 0..63
    const int vch  = tid & 3;             // chunk 0..3 (u32 offset vch*4)
    const __nv_bfloat16* vph = Vph + (size_t)vrow * SEQ + vch * 8;
    const __nv_bfloat16* vpl = Vpl + (size_t)vrow * SEQ + vch * 8;
    const uint32_t vdst = (vrow * SK + vch * 4) * 4;   // byte offset within plane

    float c[2][4][4];
#pragma unroll
    for (int mt = 0; mt < 2; ++mt)
#pragma unroll
        for (int nt = 0; nt < 4; ++nt)
#pragma unroll
            for (int i = 0; i < 4; ++i) c[mt][nt][i] = 0.0f;

    float4 pa[4];

    auto v_async = [&](int st, int kt) {
        const uint32_t base = dsma + (st * AV_STAGE) * 4;
        cp_async16(base + 5120 * 4 + vdst, vph + kt);
        cp_async16(base + 6400 * 4 + vdst, vpl + kt);
        CP_COMMIT();
    };

    // normalize + writeback + split + STS for the P tile
    auto a_stage = [&](uint32_t* base, float* wb_ptr) {
        uint32_t harr[8], larr[8];
#pragma unroll
        for (int j = 0; j < 4; ++j) {
            float4 vv = make_float4(pa[j].x * inv, pa[j].y * inv,
                                    pa[j].z * inv, pa[j].w * inv);
            *(float4*)(wb_ptr + j * 4) = vv;   // normalized attn weights
            split2(vv.x, vv.y, harr[j * 2], larr[j * 2]);
            split2(vv.z, vv.w, harr[j * 2 + 1], larr[j * 2 + 1]);
        }
        *(uint4*)&base[arow * SK + asu]            = *(uint4*)harr;
        *(uint4*)&base[arow * SK + asu + 4]        = *(uint4*)(harr + 4);
        *(uint4*)&base[2560 + arow * SK + asu]     = *(uint4*)larr;
        *(uint4*)&base[2560 + arow * SK + asu + 4] = *(uint4*)(larr + 4);
    };

    // prologue: stage slab 0
    v_async(0, 0);
#pragma unroll
    for (int j = 0; j < 4; ++j) pa[j] = *(const float4*)(apw + j * 4);
    a_stage(dsm, apw);
    CP_WAIT0();
    __syncthreads();

    int stg = 0;
#pragma unroll 1
    for (int kt = 0; kt < SEQ; kt += 32) {
        const bool nx = (kt + 32 < SEQ);
        if (nx) {
            v_async(stg ^ 1, kt + 32);
#pragma unroll
            for (int j = 0; j < 4; ++j)
                pa[j] = *(const float4*)(apw + kt + 32 + j * 4);
        }

        const uint32_t sb = dsma + stg * (AV_STAGE * 4);
        const uint32_t aAh = sb + ((wm * 32 + a_r) * SK + a_c) * 4;
        const uint32_t aAl = aAh + 2560 * 4;
        const uint32_t aBh = sb + 5120 * 4 + ((wn * 32 + b_r) * SK + b_c) * 4;
        const uint32_t aBl = aBh + 1280 * 4;

#pragma unroll
        for (int k16 = 0; k16 < 2; ++k16) {
            const uint32_t ko = k16 * 8 * 4;
            uint32_t ah[2][4], al[2][4], bh[2][4], bl[2][4];
#pragma unroll
            for (int mt = 0; mt < 2; ++mt) {
                ldsm4(ah[mt], aAh + mt * (16 * SK * 4) + ko);
                ldsm4(al[mt], aAl + mt * (16 * SK * 4) + ko);
            }
#pragma unroll
            for (int np = 0; np < 2; ++np) {
                ldsm4(bh[np], aBh + np * (16 * SK * 4) + ko);
                ldsm4(bl[np], aBl + np * (16 * SK * 4) + ko);
            }
#pragma unroll
            for (int mt = 0; mt < 2; ++mt)
#pragma unroll
                for (int nt = 0; nt < 4; ++nt)
                    mma16816(c[mt][nt], ah[mt], &bh[nt >> 1][(nt & 1) * 2]);
#pragma unroll
            for (int mt = 0; mt < 2; ++mt)
#pragma unroll
                for (int nt = 0; nt < 4; ++nt)
                    mma16816(c[mt][nt], ah[mt], &bl[nt >> 1][(nt & 1) * 2]);
#pragma unroll
            for (int mt = 0; mt < 2; ++mt)
#pragma unroll
                for (int nt = 0; nt < 4; ++nt)
                    mma16816(c[mt][nt], al[mt], &bh[nt >> 1][(nt & 1) * 2]);
        }

        if (nx) {
            a_stage(dsm + (stg ^ 1) * AV_STAGE, apw + kt + 32);
            CP_WAIT0();
        }
        __syncthreads();
        stg ^= 1;
    }

    const int b = z >> 4, hh = z & 15;
#pragma unroll
    for (int mt = 0; mt < 2; ++mt) {
#pragma unroll
        for (int nt = 0; nt < 4; ++nt) {
            const int q0 = bm + wm * 32 + mt * 16 + g;
            const int d0 = wn * 32 + nt * 8 + tg * 2;
            const size_t o0 = ((size_t)(b * SEQ + q0)) * EMBED + hh * HDIM + d0;
            const size_t o1 = ((size_t)(b * SEQ + q0 + 8)) * EMBED + hh * HDIM + d0;
            uint32_t h0, l0, h1, l1;
            split2(c[mt][nt][0], c[mt][nt][1], h0, l0);
            split2(c[mt][nt][2], c[mt][nt][3], h1, l1);
            *(uint32_t*)(g_AOh + o0) = h0;
            *(uint32_t*)(g_AOl + o0) = l0;
            *(uint32_t*)(g_AOh + o1) = h1;
            *(uint32_t*)(g_AOl + o1) = l1;
        }
    }
}

// ---------------------------------------------------------------------------
// launch
// ---------------------------------------------------------------------------
extern "C" void kernel_launch(void* const* d_in, const int* in_sizes, int n_in,
                              void* d_out, int out_size)
{
    (void)in_sizes; (void)n_in; (void)out_size;
    const float* query = (const float*)d_in[0];
    const float* key   = (const float*)d_in[1];
    const float* value = (const float*)d_in[2];
    const float* q_w   = (const float*)d_in[3];
    const float* q_b   = (const float*)d_in[4];
    const float* k_w   = (const float*)d_in[5];
    const float* k_b   = (const float*)d_in[6];
    const float* v_w   = (const float*)d_in[7];
    const float* v_b   = (const float*)d_in[8];
    const float* o_w   = (const float*)d_in[9];
    const float* o_b   = (const float*)d_in[10];

    float* out  = (float*)d_out;                 // [B,S,E]
    float* attn = out + OUT_ELEMS;               // [B,H,S,S]

    float* pPS;
    cudaGetSymbolAddress((void**)&pPS, g_psum);
    __nv_bfloat16 *pAOh, *pAOl, *pQh, *pQl, *pKh, *pKl, *pWh, *pWl;
    cudaGetSymbolAddress((void**)&pAOh, g_AOh);
    cudaGetSymbolAddress((void**)&pAOl, g_AOl);
    cudaGetSymbolAddress((void**)&pQh, g_Qh);
    cudaGetSymbolAddress((void**)&pQl, g_Ql);
    cudaGetSymbolAddress((void**)&pKh, g_Kh);
    cudaGetSymbolAddress((void**)&pKl, g_Kl);
    cudaGetSymbolAddress((void**)&pWh, g_Wh);
    cudaGetSymbolAddress((void**)&pWl, g_Wl);

    static bool attr_done = false;
    if (!attr_done) {
        cudaFuncSetAttribute(qkv_proj_kernel,
                             cudaFuncAttributeMaxDynamicSharedMemorySize, GEMM_SMEM);
        cudaFuncSetAttribute(gemm_s_kernel,
                             cudaFuncAttributeMaxDynamicSharedMemorySize, GEMM_SMEM);
        cudaFuncSetAttribute(av_mma_kernel,
                             cudaFuncAttributeMaxDynamicSharedMemorySize, AV_SMEM);
        attr_done = true;
    }

    // 0) split all fp32 operands into bf16 hi/lo once
    dim3 pgrid(MTOT * EMBED / 4 / 256, 1, 7);
    prep_split_kernel<<<pgrid, 256>>>(query, key, value, q_w, k_w, v_w, o_w);

    // 1) fused Q/K/V projections (split-bf16 outputs; V transposed)
    dim3 qkvgrid(EMBED / 128, MTOT / 128, 3);    // (8, 32, 3)
    qkv_proj_kernel<<<qkvgrid, 256, GEMM_SMEM>>>(q_b, k_b, v_b);

    // 2) scores: attn[z] = exp((Q_z @ K_z^T) * 0.125) unnormalized + psum
    dim3 sgrid(SEQ / 128, SEQ / 128, ZTOT);      // (16, 16, 32)
    gemm_s_kernel<<<sgrid, 256, GEMM_SMEM>>>(pQh, pQl, pKh, pKl, nullptr, attn,
                                             HDIM, HDIM, SEQ, HDIM,
                                             (size_t)SEQ * HDIM, (size_t)SEQ * HDIM,
                                             (size_t)SEQ * SEQ, 3, 0.125f, pPS);

    // 3) av: normalize attn in place + AO = P @ V (split outputs)
    dim3 avgrid(SEQ / 128, ZTOT);                // (16, 32)
    av_mma_kernel<<<avgrid, 256, AV_SMEM>>>(attn, pPS);

    // 4) output projection (fp32 out + bias)
    dim3 ogrid(EMBED / 128, MTOT / 128, 1);      // (8, 32)
    gemm_s_kernel<<<ogrid, 256, GEMM_SMEM>>>(pAOh, pAOl,
                                             pWh + (size_t)3 * EMBED * EMBED,
                                             pWl + (size_t)3 * EMBED * EMBED,
                                             o_b, out,
                                             EMBED, EMBED, EMBED, EMBED, 0, 0, 0,
                                             0, 1.0f, nullptr);
}